// round 10
// baseline (speedup 1.0000x reference)
#include <cuda_runtime.h>

#define N_NODES 16384
#define N_EDGES 131072
#define F_IN 6
#define S_DIM 4
#define G_NUM 256
#define H_DIM 30
#define C1 32
#define C2 64
#define C3 32
#define K1 192          /* 30*6 wk1 + 6 bk1 + 6 root1 */
#define K2 1024         /* permuted: j*64+2*c1+par (h=2j+par) | 960+c1 bk | 992+c1 root */

// ---------------- scratch ----------------------------------------------------
__device__ float g_H1[N_EDGES * H_DIM];
__device__ float g_H2[N_EDGES * H_DIM];
__device__ float g_P2[N_NODES * K2];
__device__ float g_X1[N_NODES * C1];
__device__ float g_XW[N_NODES * C3];
__device__ float g_W1[K1 * C1];
__device__ float g_W2[K2 * C2];
__device__ int g_deg[N_NODES];          // left zero by k_gcn for the next call
__device__ int g_rowptr[N_NODES + 1];
__device__ int g_cursor[N_NODES];
__device__ int g_csr[N_EDGES];
__device__ int g_chainflag[65];         // prefix+1; 0 = not ready
__device__ int g_done;

// ---------------- packed f32x2 helpers ---------------------------------------
__device__ __forceinline__ unsigned long long pk2(float lo, float hi) {
    unsigned long long r;
    asm("mov.b64 %0, {%1, %2};" : "=l"(r) : "f"(lo), "f"(hi));
    return r;
}
__device__ __forceinline__ void upk2(unsigned long long v, float& lo, float& hi) {
    asm("mov.b64 {%0, %1}, %2;" : "=f"(lo), "=f"(hi) : "l"(v));
}
__device__ __forceinline__ unsigned long long fma2(unsigned long long a,
                                                   unsigned long long b,
                                                   unsigned long long c) {
    unsigned long long d;
    asm("fma.rn.f32x2 %0, %1, %2, %3;" : "=l"(d) : "l"(a), "l"(b), "l"(c));
    return d;
}

// ---------------- kernel 1: edge MLPs + tgt hist + prep (merged) -------------
__global__ void k_mlp(const float* __restrict__ e, const int* __restrict__ tgt,
                      const float* __restrict__ w0a, const float* __restrict__ b0a,
                      const float* __restrict__ w1a, const float* __restrict__ b1a,
                      const float* __restrict__ w0b, const float* __restrict__ b0b,
                      const float* __restrict__ w1b, const float* __restrict__ b1b,
                      float* __restrict__ out, int out_n,
                      const float* __restrict__ e1_wk, const float* __restrict__ e1_bk,
                      const float* __restrict__ e1_root,
                      const float* __restrict__ e2_wk, const float* __restrict__ e2_bk,
                      const float* __restrict__ e2_root) {
    __shared__ float sw0[2][S_DIM * H_DIM];
    __shared__ float sb0[2][H_DIM];
    __shared__ float sw1[2][H_DIM * H_DIM];
    __shared__ float sb1[2][H_DIM];
    for (int i = threadIdx.x; i < S_DIM * H_DIM; i += blockDim.x) {
        sw0[0][i] = w0a[i]; sw0[1][i] = w0b[i];
    }
    for (int i = threadIdx.x; i < H_DIM; i += blockDim.x) {
        sb0[0][i] = b0a[i]; sb0[1][i] = b0b[i];
        sb1[0][i] = b1a[i]; sb1[1][i] = b1b[i];
    }
    for (int i = threadIdx.x; i < H_DIM * H_DIM; i += blockDim.x) {
        sw1[0][i] = w1a[i]; sw1[1][i] = w1b[i];
    }
    __syncthreads();

    int eid = blockIdx.x * blockDim.x + threadIdx.x;
    if (eid >= N_EDGES) return;

    // ---- prep duties spread over the grid ----
    if (eid < out_n) out[eid] = 0.f;
    if (eid < K1 * C1) {
        int k = eid / C1, c = eid % C1;
        float v;
        if (k < 180)      { int h = k / 6, f = k % 6; v = e1_wk[h * (F_IN * C1) + f * C1 + c]; }
        else if (k < 186) { int f = k - 180;          v = e1_bk[f * C1 + c]; }
        else              { int f = k - 186;          v = e1_root[f * C1 + c]; }
        g_W1[eid] = v;
    }
    if (eid < K2 * C2) {
        int k = eid / C2, c = eid % C2;
        float v;
        if (k < 960) {      // permuted: k = j*64 + 2*c1 + par, h = 2j+par
            int j = k >> 6, r = k & 63, c1 = r >> 1, par = r & 1, h = 2 * j + par;
            v = e2_wk[h * (C1 * C2) + c1 * C2 + c];
        }
        else if (k < 992) { int c1 = k - 960; v = e2_bk[c1 * C2 + c]; }
        else              { int c1 = k - 992; v = e2_root[c1 * C2 + c]; }
        g_W2[eid] = v;
    }

    atomicAdd(&g_deg[tgt[eid]], 1);

    float4 ev4 = *reinterpret_cast<const float4*>(e + eid * 4);
    float ev[4] = {ev4.x, ev4.y, ev4.z, ev4.w};

    #pragma unroll
    for (int set = 0; set < 2; set++) {
        unsigned long long h0p[15];
        #pragma unroll
        for (int j = 0; j < 15; j++)
            h0p[j] = *reinterpret_cast<const unsigned long long*>(&sb0[set][2 * j]);
        #pragma unroll
        for (int s = 0; s < S_DIM; s++) {
            unsigned long long ep = pk2(ev[s], ev[s]);
            #pragma unroll
            for (int j = 0; j < 15; j++) {
                unsigned long long wp =
                    *reinterpret_cast<const unsigned long long*>(&sw0[set][s * H_DIM + 2 * j]);
                h0p[j] = fma2(wp, ep, h0p[j]);
            }
        }
        float h0[H_DIM];
        #pragma unroll
        for (int j = 0; j < 15; j++) {
            float a, b;
            upk2(h0p[j], a, b);
            h0[2 * j] = fmaxf(a, 0.f);
            h0[2 * j + 1] = fmaxf(b, 0.f);
        }
        unsigned long long h1p[15];
        #pragma unroll
        for (int j = 0; j < 15; j++)
            h1p[j] = *reinterpret_cast<const unsigned long long*>(&sb1[set][2 * j]);
        #pragma unroll 6
        for (int k = 0; k < H_DIM; k++) {
            unsigned long long hp = pk2(h0[k], h0[k]);
            #pragma unroll
            for (int j = 0; j < 15; j++) {
                unsigned long long wp =
                    *reinterpret_cast<const unsigned long long*>(&sw1[set][k * H_DIM + 2 * j]);
                h1p[j] = fma2(wp, hp, h1p[j]);
            }
        }
        float* dst = (set == 0 ? g_H1 : g_H2) + eid * H_DIM;
        #pragma unroll
        for (int j = 0; j < 15; j++) {
            float a, b;
            upk2(h1p[j], a, b);
            dst[2 * j] = fmaxf(a, 0.f);
            dst[2 * j + 1] = fmaxf(b, 0.f);
        }
    }
}

// ---------------- kernel 2: full CSR build in ONE kernel ----------------------
__global__ void k_csr(const int* __restrict__ tgt) {
    __shared__ int sh[256];
    __shared__ int s_prefix;
    int tid = threadIdx.x, b = blockIdx.x;
    int i = b * 256 + tid;
    int v = g_deg[i];
    sh[tid] = v;
    __syncthreads();
    int sum = v;
    for (int d = 1; d < 256; d <<= 1) {
        int t = (tid >= d) ? sh[tid - d] : 0;
        __syncthreads();
        sum += t;
        sh[tid] = sum;
        __syncthreads();
    }
    if (tid == 0) {
        int p = 0;
        if (b > 0) {
            while ((p = atomicAdd(&g_chainflag[b], 0)) == 0) {}
            p -= 1;
        }
        s_prefix = p;
        atomicExch(&g_chainflag[b + 1], p + sh[255] + 1);
    }
    __syncthreads();
    int r = s_prefix + sum - v;
    g_rowptr[i] = r;
    g_cursor[i] = r;
    if (b == 63 && tid == 255) g_rowptr[N_NODES] = N_EDGES;
    __threadfence();
    __syncthreads();
    if (tid == 0) atomicAdd(&g_done, 1);
    if (tid == 0) { while (atomicAdd(&g_done, 0) < 64) {} }
    __syncthreads();
    for (int e = b * 2048 + tid; e < (b + 1) * 2048; e += 256) {
        int p = atomicAdd(&g_cursor[tgt[e]], 1);
        g_csr[p] = e;
    }
}

// ---------------- kernel 3: fused ECC1 (P1 rows in smem + mini-GEMM) ---------
// block = 256 threads = 8 warps = 8 targets; lane = K1-row (0..29 wk,30 bk,31 root)
__global__ void k_ecc1(const float* __restrict__ x, const int* __restrict__ src,
                       const float* __restrict__ bias1) {
    __shared__ float sW1[K1 * C1];      // 24 KB
    __shared__ float sP1[8][K1];        // 6 KB
    int tid = threadIdx.x;
    int w = tid >> 5, lane = tid & 31;
    int t = blockIdx.x * 8 + w;
    for (int i = tid; i < K1 * C1 / 4; i += 256)
        ((float4*)sW1)[i] = ((const float4*)g_W1)[i];

    int rs = g_rowptr[t], re = g_rowptr[t + 1];
    unsigned long long acc2[3] = {0ull, 0ull, 0ull};
    float hv_fix = (lane == 30) ? 1.f : 0.f;
    int pos = rs;
    int eid = 0, s = 0;
    if (pos < re) { eid = g_csr[pos]; s = src[eid]; }
    while (pos < re) {
        // warp-uniform x row (3 x LDG.64 broadcast)
        const unsigned long long* xp = reinterpret_cast<const unsigned long long*>(x + s * 6);
        unsigned long long x01 = xp[0], x23 = xp[1], x45 = xp[2];
        float hv = (lane < 30) ? g_H1[eid * H_DIM + lane] : hv_fix;
        int pos2 = pos + 1;
        int eid2 = 0, s2 = 0;
        if (pos2 < re) { eid2 = g_csr[pos2]; s2 = src[eid2]; }
        unsigned long long hp = pk2(hv, hv);
        acc2[0] = fma2(x01, hp, acc2[0]);
        acc2[1] = fma2(x23, hp, acc2[1]);
        acc2[2] = fma2(x45, hp, acc2[2]);
        pos = pos2; eid = eid2; s = s2;
    }
    float acc[6];
    upk2(acc2[0], acc[0], acc[1]);
    upk2(acc2[1], acc[2], acc[3]);
    upk2(acc2[2], acc[4], acc[5]);
    if (lane == 31) {
        #pragma unroll
        for (int f = 0; f < 6; f++) acc[f] = x[t * 6 + f];
    }
    #pragma unroll
    for (int f = 0; f < 6; f++) sP1[w][lane * 6 + f] = acc[f];
    __syncthreads();

    float av = bias1[lane];
    const float* pr = sP1[w];
    #pragma unroll 8
    for (int k = 0; k < K1; k += 4) {
        float4 p = *reinterpret_cast<const float4*>(pr + k);
        av += p.x * sW1[(k + 0) * C1 + lane];
        av += p.y * sW1[(k + 1) * C1 + lane];
        av += p.z * sW1[(k + 2) * C1 + lane];
        av += p.w * sW1[(k + 3) * C1 + lane];
    }
    g_X1[t * C1 + lane] = fmaxf(av, 0.f);
}

// ---------------- kernel 4: P2 per-target outer-product sums -----------------
// lane = c1; h-pairs via warp-uniform LDG.64 broadcasts; f32x2 accumulate.
// Permuted store: k' = j*64 + 2*lane + par  (h = 2j+par)
__global__ void k_p2(const int* __restrict__ src) {
    int t = (blockIdx.x * blockDim.x + threadIdx.x) >> 5;
    int lane = threadIdx.x & 31;
    if (t >= N_NODES) return;
    int rs = g_rowptr[t], re = g_rowptr[t + 1];
    unsigned long long acc2[15];
    #pragma unroll
    for (int j = 0; j < 15; j++) acc2[j] = 0ull;
    float acc30 = 0.f;
    int pos = rs;
    int eid = 0, s = 0;
    if (pos < re) { eid = g_csr[pos]; s = src[eid]; }
    while (pos < re) {
        float x1v = g_X1[s * C1 + lane];
        const unsigned long long* hp = reinterpret_cast<const unsigned long long*>(g_H2 + eid * H_DIM);
        int pos2 = pos + 1;
        int eid2 = 0, s2 = 0;
        if (pos2 < re) { eid2 = g_csr[pos2]; s2 = src[eid2]; }
        unsigned long long xp = pk2(x1v, x1v);
        #pragma unroll
        for (int j = 0; j < 15; j++)
            acc2[j] = fma2(hp[j], xp, acc2[j]);
        acc30 += x1v;
        pos = pos2; eid = eid2; s = s2;
    }
    float* base = g_P2 + t * K2;
    #pragma unroll
    for (int j = 0; j < 15; j++)
        *reinterpret_cast<unsigned long long*>(base + j * 64 + lane * 2) = acc2[j];
    base[960 + lane] = acc30;
    base[992 + lane] = g_X1[t * C1 + lane];
}

// ---------------- kernel 5: GEMM2 + fused GCN-xw -----------------------------
__global__ void k_gemm2(const float* __restrict__ bias2, const float* __restrict__ gcnW) {
    __shared__ float smu[128 * 68];
    __shared__ float sW[C2 * C3];
    float* sA = smu;
    float* sB = smu + 4160;
    int tid = threadIdx.x;
    int nb = blockIdx.x * 128;
    for (int i = tid; i < C2 * C3; i += 256) sW[i] = gcnW[i];

    int tx = tid & 15;
    int ty = tid >> 4;
    unsigned long long acc2[4][4];
    #pragma unroll
    for (int p = 0; p < 4; p++)
        #pragma unroll
        for (int j = 0; j < 4; j++) acc2[p][j] = 0ull;

    for (int k0 = 0; k0 < K2; k0 += 32) {
        int lrow = tid >> 3, lk4 = (tid & 7) * 4;
        #pragma unroll
        for (int j = 0; j < 4; j++) {
            int row = lrow + 32 * j;
            float4 v = *reinterpret_cast<const float4*>(&g_P2[(nb + row) * K2 + k0 + lk4]);
            sA[(lk4 + 0) * 130 + row] = v.x;
            sA[(lk4 + 1) * 130 + row] = v.y;
            sA[(lk4 + 2) * 130 + row] = v.z;
            sA[(lk4 + 3) * 130 + row] = v.w;
        }
        {
            int kr = tid >> 3, c8 = (tid & 7) * 8;
            float4 v0 = *reinterpret_cast<const float4*>(&g_W2[(k0 + kr) * C2 + c8]);
            float4 v1 = *reinterpret_cast<const float4*>(&g_W2[(k0 + kr) * C2 + c8 + 4]);
            *reinterpret_cast<float4*>(&sB[kr * 64 + c8])     = v0;
            *reinterpret_cast<float4*>(&sB[kr * 64 + c8 + 4]) = v1;
        }
        __syncthreads();
        #pragma unroll 8
        for (int k = 0; k < 32; k++) {
            unsigned long long a[4];
            #pragma unroll
            for (int p = 0; p < 4; p++)
                a[p] = *reinterpret_cast<const unsigned long long*>(&sA[k * 130 + ty * 8 + p * 2]);
            float4 b = *reinterpret_cast<const float4*>(&sB[k * 64 + tx * 4]);
            float bb[4] = {b.x, b.y, b.z, b.w};
            #pragma unroll
            for (int j = 0; j < 4; j++) {
                unsigned long long bp = pk2(bb[j], bb[j]);
                #pragma unroll
                for (int p = 0; p < 4; p++) acc2[p][j] = fma2(a[p], bp, acc2[p][j]);
            }
        }
        __syncthreads();
    }
    float* sX2 = smu;
    #pragma unroll
    for (int p = 0; p < 4; p++)
        #pragma unroll
        for (int j = 0; j < 4; j++) {
            float v0, v1;
            upk2(acc2[p][j], v0, v1);
            int c = tx * 4 + j;
            float bs = bias2[c];
            int r0 = ty * 8 + p * 2;
            sX2[r0 * 68 + c]       = fmaxf(v0 + bs, 0.f);
            sX2[(r0 + 1) * 68 + c] = fmaxf(v1 + bs, 0.f);
        }
    __syncthreads();
    #pragma unroll
    for (int i = 0; i < 16; i++) {
        int o = tid + i * 256;
        int row = o >> 5, c3 = o & 31;
        float a = 0.f;
        #pragma unroll 8
        for (int c2 = 0; c2 < C2; c2++)
            a += sX2[row * 68 + c2] * sW[c2 * C3 + c3];
        g_XW[(nb + row) * C3 + c3] = a;
    }
}

// ---------------- kernel 6: GCN agg + bias + relu + pool + state reset -------
__global__ void k_gcn(const int* __restrict__ src, const float* __restrict__ gw,
                      const int* __restrict__ seg, const float* __restrict__ gcn_b,
                      float* __restrict__ out) {
    int gthr = blockIdx.x * blockDim.x + threadIdx.x;
    int t = gthr >> 5;
    int lane = threadIdx.x & 31;
    if (t >= N_NODES) return;
    if (lane == 0) g_deg[t] = 0;
    if (gthr < 65) g_chainflag[gthr] = 0;
    if (gthr == 65) g_done = 0;

    int rs = g_rowptr[t], re = g_rowptr[t + 1];
    float acc = gw[N_EDGES + t] * g_XW[t * C3 + lane];    // self loop
    int pos = rs;
    int eid = 0, s = 0;
    if (pos < re) { eid = g_csr[pos]; s = src[eid]; }
    while (pos < re) {
        float xv = g_XW[s * C3 + lane];
        float wv = gw[eid];
        int pos2 = pos + 1;
        int eid2 = 0, s2 = 0;
        if (pos2 < re) { eid2 = g_csr[pos2]; s2 = src[eid2]; }
        acc += wv * xv;
        pos = pos2; eid = eid2; s = s2;
    }
    float v = fmaxf(acc + gcn_b[lane], 0.f);
    atomicAdd(&out[seg[t] * C3 + lane], v);
}

// =============================================================================
extern "C" void kernel_launch(void* const* d_in, const int* in_sizes, int n_in,
                              void* d_out, int out_size) {
    const float* x       = (const float*)d_in[0];
    const float* e       = (const float*)d_in[1];
    const int*   src     = (const int*)d_in[2];
    const int*   tgt     = (const int*)d_in[3];
    const int*   seg     = (const int*)d_in[4];
    const float* gw      = (const float*)d_in[7];
    const float* e1_w0   = (const float*)d_in[8];
    const float* e1_b0   = (const float*)d_in[9];
    const float* e1_w1   = (const float*)d_in[10];
    const float* e1_b1   = (const float*)d_in[11];
    const float* e1_wk   = (const float*)d_in[12];
    const float* e1_bk   = (const float*)d_in[13];
    const float* e1_root = (const float*)d_in[14];
    const float* e1_bias = (const float*)d_in[15];
    const float* e2_w0   = (const float*)d_in[16];
    const float* e2_b0   = (const float*)d_in[17];
    const float* e2_w1   = (const float*)d_in[18];
    const float* e2_b1   = (const float*)d_in[19];
    const float* e2_wk   = (const float*)d_in[20];
    const float* e2_bk   = (const float*)d_in[21];
    const float* e2_root = (const float*)d_in[22];
    const float* e2_bias = (const float*)d_in[23];
    const float* gcn_W   = (const float*)d_in[24];
    const float* gcn_b   = (const float*)d_in[25];
    float* out = (float*)d_out;

    k_mlp<<<N_EDGES / 256, 256>>>(e, tgt, e1_w0, e1_b0, e1_w1, e1_b1,
                                  e2_w0, e2_b0, e2_w1, e2_b1,
                                  out, out_size,
                                  e1_wk, e1_bk, e1_root, e2_wk, e2_bk, e2_root);
    k_csr<<<64, 256>>>(tgt);
    k_ecc1<<<N_NODES / 8, 256>>>(x, src, e1_bias);
    k_p2<<<(N_NODES * 32) / 256, 256>>>(src);
    k_gemm2<<<N_NODES / 128, 256>>>(e2_bias, gcn_W);
    k_gcn<<<(N_NODES * 32) / 256, 256>>>(src, gw, seg, gcn_b, out);
}

// round 11
// speedup vs baseline: 1.0065x; 1.0065x over previous
#include <cuda_runtime.h>

#define N_NODES 16384
#define N_EDGES 131072
#define F_IN 6
#define S_DIM 4
#define G_NUM 256
#define H_DIM 30
#define C1 32
#define C2 64
#define C3 32
#define K1 192          /* 30*6 wk1 + 6 bk1 + 6 root1 */
#define K2 1024         /* permuted: j*64+2*c1+par (h=2j+par) | 960+c1 bk | 992+c1 root */

// ---------------- scratch ----------------------------------------------------
__device__ float g_H1[N_EDGES * H_DIM];
__device__ float g_H2[N_EDGES * H_DIM];
__device__ float g_P2[N_NODES * K2];
__device__ float g_X1[N_NODES * C1];
__device__ float g_XW[N_NODES * C3];
__device__ float g_W1[K1 * C1];
__device__ float g_W2[K2 * C2];
__device__ int g_deg[N_NODES];          // left zero by k_gcn for the next call
__device__ int g_rowptr[N_NODES + 1];
__device__ int g_cursor[N_NODES];
__device__ int g_csr[N_EDGES];
__device__ int g_chainflag[65];         // prefix+1; 0 = not ready
__device__ int g_done;

// ---------------- packed f32x2 helpers ---------------------------------------
__device__ __forceinline__ unsigned long long pk2(float lo, float hi) {
    unsigned long long r;
    asm("mov.b64 %0, {%1, %2};" : "=l"(r) : "f"(lo), "f"(hi));
    return r;
}
__device__ __forceinline__ void upk2(unsigned long long v, float& lo, float& hi) {
    asm("mov.b64 {%0, %1}, %2;" : "=f"(lo), "=f"(hi) : "l"(v));
}
__device__ __forceinline__ unsigned long long fma2(unsigned long long a,
                                                   unsigned long long b,
                                                   unsigned long long c) {
    unsigned long long d;
    asm("fma.rn.f32x2 %0, %1, %2, %3;" : "=l"(d) : "l"(a), "l"(b), "l"(c));
    return d;
}

// ---------------- kernel 1: edge MLPs + tgt hist + prep (merged) -------------
__global__ void k_mlp(const float* __restrict__ e, const int* __restrict__ tgt,
                      const float* __restrict__ w0a, const float* __restrict__ b0a,
                      const float* __restrict__ w1a, const float* __restrict__ b1a,
                      const float* __restrict__ w0b, const float* __restrict__ b0b,
                      const float* __restrict__ w1b, const float* __restrict__ b1b,
                      float* __restrict__ out, int out_n,
                      const float* __restrict__ e1_wk, const float* __restrict__ e1_bk,
                      const float* __restrict__ e1_root,
                      const float* __restrict__ e2_wk, const float* __restrict__ e2_bk,
                      const float* __restrict__ e2_root) {
    __shared__ float sw0[2][S_DIM * H_DIM];
    __shared__ float sb0[2][H_DIM];
    __shared__ float sw1[2][H_DIM * H_DIM];
    __shared__ float sb1[2][H_DIM];
    for (int i = threadIdx.x; i < S_DIM * H_DIM; i += blockDim.x) {
        sw0[0][i] = w0a[i]; sw0[1][i] = w0b[i];
    }
    for (int i = threadIdx.x; i < H_DIM; i += blockDim.x) {
        sb0[0][i] = b0a[i]; sb0[1][i] = b0b[i];
        sb1[0][i] = b1a[i]; sb1[1][i] = b1b[i];
    }
    for (int i = threadIdx.x; i < H_DIM * H_DIM; i += blockDim.x) {
        sw1[0][i] = w1a[i]; sw1[1][i] = w1b[i];
    }
    __syncthreads();

    int eid = blockIdx.x * blockDim.x + threadIdx.x;
    if (eid >= N_EDGES) return;

    // ---- prep duties spread over the grid ----
    if (eid < out_n) out[eid] = 0.f;
    if (eid < K1 * C1) {
        int k = eid / C1, c = eid % C1;
        float v;
        if (k < 180)      { int h = k / 6, f = k % 6; v = e1_wk[h * (F_IN * C1) + f * C1 + c]; }
        else if (k < 186) { int f = k - 180;          v = e1_bk[f * C1 + c]; }
        else              { int f = k - 186;          v = e1_root[f * C1 + c]; }
        g_W1[eid] = v;
    }
    if (eid < K2 * C2) {
        int k = eid / C2, c = eid % C2;
        float v;
        if (k < 960) {      // permuted: k = j*64 + 2*c1 + par, h = 2j+par
            int j = k >> 6, r = k & 63, c1 = r >> 1, par = r & 1, h = 2 * j + par;
            v = e2_wk[h * (C1 * C2) + c1 * C2 + c];
        }
        else if (k < 992) { int c1 = k - 960; v = e2_bk[c1 * C2 + c]; }
        else              { int c1 = k - 992; v = e2_root[c1 * C2 + c]; }
        g_W2[eid] = v;
    }

    atomicAdd(&g_deg[tgt[eid]], 1);

    float4 ev4 = *reinterpret_cast<const float4*>(e + eid * 4);
    float ev[4] = {ev4.x, ev4.y, ev4.z, ev4.w};

    #pragma unroll
    for (int set = 0; set < 2; set++) {
        unsigned long long h0p[15];
        #pragma unroll
        for (int j = 0; j < 15; j++)
            h0p[j] = *reinterpret_cast<const unsigned long long*>(&sb0[set][2 * j]);
        #pragma unroll
        for (int s = 0; s < S_DIM; s++) {
            unsigned long long ep = pk2(ev[s], ev[s]);
            #pragma unroll
            for (int j = 0; j < 15; j++) {
                unsigned long long wp =
                    *reinterpret_cast<const unsigned long long*>(&sw0[set][s * H_DIM + 2 * j]);
                h0p[j] = fma2(wp, ep, h0p[j]);
            }
        }
        float h0[H_DIM];
        #pragma unroll
        for (int j = 0; j < 15; j++) {
            float a, b;
            upk2(h0p[j], a, b);
            h0[2 * j] = fmaxf(a, 0.f);
            h0[2 * j + 1] = fmaxf(b, 0.f);
        }
        unsigned long long h1p[15];
        #pragma unroll
        for (int j = 0; j < 15; j++)
            h1p[j] = *reinterpret_cast<const unsigned long long*>(&sb1[set][2 * j]);
        #pragma unroll 6
        for (int k = 0; k < H_DIM; k++) {
            unsigned long long hp = pk2(h0[k], h0[k]);
            #pragma unroll
            for (int j = 0; j < 15; j++) {
                unsigned long long wp =
                    *reinterpret_cast<const unsigned long long*>(&sw1[set][k * H_DIM + 2 * j]);
                h1p[j] = fma2(wp, hp, h1p[j]);
            }
        }
        float* dst = (set == 0 ? g_H1 : g_H2) + eid * H_DIM;
        #pragma unroll
        for (int j = 0; j < 15; j++) {
            float a, b;
            upk2(h1p[j], a, b);
            dst[2 * j] = fmaxf(a, 0.f);
            dst[2 * j + 1] = fmaxf(b, 0.f);
        }
    }
}

// ---------------- kernel 2: full CSR build in ONE kernel ----------------------
__global__ void k_csr(const int* __restrict__ tgt) {
    __shared__ int sh[256];
    __shared__ int s_prefix;
    int tid = threadIdx.x, b = blockIdx.x;
    int i = b * 256 + tid;
    int v = g_deg[i];
    sh[tid] = v;
    __syncthreads();
    int sum = v;
    for (int d = 1; d < 256; d <<= 1) {
        int t = (tid >= d) ? sh[tid - d] : 0;
        __syncthreads();
        sum += t;
        sh[tid] = sum;
        __syncthreads();
    }
    if (tid == 0) {
        int p = 0;
        if (b > 0) {
            while ((p = atomicAdd(&g_chainflag[b], 0)) == 0) {}
            p -= 1;
        }
        s_prefix = p;
        atomicExch(&g_chainflag[b + 1], p + sh[255] + 1);
    }
    __syncthreads();
    int r = s_prefix + sum - v;
    g_rowptr[i] = r;
    g_cursor[i] = r;
    if (b == 63 && tid == 255) g_rowptr[N_NODES] = N_EDGES;
    __threadfence();
    __syncthreads();
    if (tid == 0) atomicAdd(&g_done, 1);
    if (tid == 0) { while (atomicAdd(&g_done, 0) < 64) {} }
    __syncthreads();
    for (int e = b * 2048 + tid; e < (b + 1) * 2048; e += 256) {
        int p = atomicAdd(&g_cursor[tgt[e]], 1);
        g_csr[p] = e;
    }
}

// ---------------- kernel 3: fused ECC1 (P1 rows in smem + mini-GEMM) ---------
// block = 256 threads = 8 warps = 8 targets; lane = K1-row (0..29 wk,30 bk,31 root)
__global__ void k_ecc1(const float* __restrict__ x, const int* __restrict__ src,
                       const float* __restrict__ bias1) {
    __shared__ float sW1[K1 * C1];      // 24 KB
    __shared__ float sP1[8][K1];        // 6 KB
    int tid = threadIdx.x;
    int w = tid >> 5, lane = tid & 31;
    int t = blockIdx.x * 8 + w;
    for (int i = tid; i < K1 * C1 / 4; i += 256)
        ((float4*)sW1)[i] = ((const float4*)g_W1)[i];

    int rs = g_rowptr[t], re = g_rowptr[t + 1];
    unsigned long long acc2[3] = {0ull, 0ull, 0ull};
    float hv_fix = (lane == 30) ? 1.f : 0.f;
    int pos = rs;
    int eid = 0, s = 0;
    if (pos < re) { eid = g_csr[pos]; s = src[eid]; }
    while (pos < re) {
        // warp-uniform x row (3 x LDG.64 broadcast)
        const unsigned long long* xp = reinterpret_cast<const unsigned long long*>(x + s * 6);
        unsigned long long x01 = xp[0], x23 = xp[1], x45 = xp[2];
        float hv = (lane < 30) ? g_H1[eid * H_DIM + lane] : hv_fix;
        int pos2 = pos + 1;
        int eid2 = 0, s2 = 0;
        if (pos2 < re) { eid2 = g_csr[pos2]; s2 = src[eid2]; }
        unsigned long long hp = pk2(hv, hv);
        acc2[0] = fma2(x01, hp, acc2[0]);
        acc2[1] = fma2(x23, hp, acc2[1]);
        acc2[2] = fma2(x45, hp, acc2[2]);
        pos = pos2; eid = eid2; s = s2;
    }
    float acc[6];
    upk2(acc2[0], acc[0], acc[1]);
    upk2(acc2[1], acc[2], acc[3]);
    upk2(acc2[2], acc[4], acc[5]);
    if (lane == 31) {
        #pragma unroll
        for (int f = 0; f < 6; f++) acc[f] = x[t * 6 + f];
    }
    #pragma unroll
    for (int f = 0; f < 6; f++) sP1[w][lane * 6 + f] = acc[f];
    __syncthreads();

    float av = bias1[lane];
    const float* pr = sP1[w];
    #pragma unroll 8
    for (int k = 0; k < K1; k += 4) {
        float4 p = *reinterpret_cast<const float4*>(pr + k);
        av += p.x * sW1[(k + 0) * C1 + lane];
        av += p.y * sW1[(k + 1) * C1 + lane];
        av += p.z * sW1[(k + 2) * C1 + lane];
        av += p.w * sW1[(k + 3) * C1 + lane];
    }
    g_X1[t * C1 + lane] = fmaxf(av, 0.f);
}

// ---------------- kernel 4: P2 per-target outer-product sums -----------------
// lane = c1. Per edge: coalesced LDG of h-row -> STS -> 15 x LDS.64 broadcast
// feeding fma.rn.f32x2. Permuted store: k' = j*64 + 2*lane + par (h = 2j+par).
__global__ void k_p2(const int* __restrict__ src) {
    __shared__ float sh[8][32];
    int tid = threadIdx.x;
    int w = tid >> 5, lane = tid & 31;
    int t = blockIdx.x * 8 + w;
    int rs = g_rowptr[t], re = g_rowptr[t + 1];
    unsigned long long acc2[15];
    #pragma unroll
    for (int j = 0; j < 15; j++) acc2[j] = 0ull;
    float acc30 = 0.f;
    int pos = rs;
    int eid = 0, s = 0;
    if (pos < re) { eid = g_csr[pos]; s = src[eid]; }
    while (pos < re) {
        float x1v = g_X1[s * C1 + lane];
        float hl = (lane < 30) ? g_H2[eid * H_DIM + lane] : 0.f;
        sh[w][lane] = hl;
        __syncwarp();
        int pos2 = pos + 1;
        int eid2 = 0, s2 = 0;
        if (pos2 < re) { eid2 = g_csr[pos2]; s2 = src[eid2]; }
        unsigned long long xp = pk2(x1v, x1v);
        const unsigned long long* hp = reinterpret_cast<const unsigned long long*>(sh[w]);
        #pragma unroll
        for (int j = 0; j < 15; j++)
            acc2[j] = fma2(hp[j], xp, acc2[j]);
        acc30 += x1v;
        __syncwarp();
        pos = pos2; eid = eid2; s = s2;
    }
    float* base = g_P2 + t * K2;
    #pragma unroll
    for (int j = 0; j < 15; j++)
        *reinterpret_cast<unsigned long long*>(base + j * 64 + lane * 2) = acc2[j];
    base[960 + lane] = acc30;
    base[992 + lane] = g_X1[t * C1 + lane];
}

// ---------------- kernel 5: GEMM2 + fused GCN-xw -----------------------------
__global__ void k_gemm2(const float* __restrict__ bias2, const float* __restrict__ gcnW) {
    __shared__ float smu[128 * 68];
    __shared__ float sW[C2 * C3];
    float* sA = smu;
    float* sB = smu + 4160;
    int tid = threadIdx.x;
    int nb = blockIdx.x * 128;
    for (int i = tid; i < C2 * C3; i += 256) sW[i] = gcnW[i];

    int tx = tid & 15;
    int ty = tid >> 4;
    unsigned long long acc2[4][4];
    #pragma unroll
    for (int p = 0; p < 4; p++)
        #pragma unroll
        for (int j = 0; j < 4; j++) acc2[p][j] = 0ull;

    for (int k0 = 0; k0 < K2; k0 += 32) {
        int lrow = tid >> 3, lk4 = (tid & 7) * 4;
        #pragma unroll
        for (int j = 0; j < 4; j++) {
            int row = lrow + 32 * j;
            float4 v = *reinterpret_cast<const float4*>(&g_P2[(nb + row) * K2 + k0 + lk4]);
            sA[(lk4 + 0) * 130 + row] = v.x;
            sA[(lk4 + 1) * 130 + row] = v.y;
            sA[(lk4 + 2) * 130 + row] = v.z;
            sA[(lk4 + 3) * 130 + row] = v.w;
        }
        {
            int kr = tid >> 3, c8 = (tid & 7) * 8;
            float4 v0 = *reinterpret_cast<const float4*>(&g_W2[(k0 + kr) * C2 + c8]);
            float4 v1 = *reinterpret_cast<const float4*>(&g_W2[(k0 + kr) * C2 + c8 + 4]);
            *reinterpret_cast<float4*>(&sB[kr * 64 + c8])     = v0;
            *reinterpret_cast<float4*>(&sB[kr * 64 + c8 + 4]) = v1;
        }
        __syncthreads();
        #pragma unroll 8
        for (int k = 0; k < 32; k++) {
            unsigned long long a[4];
            #pragma unroll
            for (int p = 0; p < 4; p++)
                a[p] = *reinterpret_cast<const unsigned long long*>(&sA[k * 130 + ty * 8 + p * 2]);
            float4 b = *reinterpret_cast<const float4*>(&sB[k * 64 + tx * 4]);
            float bb[4] = {b.x, b.y, b.z, b.w};
            #pragma unroll
            for (int j = 0; j < 4; j++) {
                unsigned long long bp = pk2(bb[j], bb[j]);
                #pragma unroll
                for (int p = 0; p < 4; p++) acc2[p][j] = fma2(a[p], bp, acc2[p][j]);
            }
        }
        __syncthreads();
    }
    float* sX2 = smu;
    #pragma unroll
    for (int p = 0; p < 4; p++)
        #pragma unroll
        for (int j = 0; j < 4; j++) {
            float v0, v1;
            upk2(acc2[p][j], v0, v1);
            int c = tx * 4 + j;
            float bs = bias2[c];
            int r0 = ty * 8 + p * 2;
            sX2[r0 * 68 + c]       = fmaxf(v0 + bs, 0.f);
            sX2[(r0 + 1) * 68 + c] = fmaxf(v1 + bs, 0.f);
        }
    __syncthreads();
    #pragma unroll
    for (int i = 0; i < 16; i++) {
        int o = tid + i * 256;
        int row = o >> 5, c3 = o & 31;
        float a = 0.f;
        #pragma unroll 8
        for (int c2 = 0; c2 < C2; c2++)
            a += sX2[row * 68 + c2] * sW[c2 * C3 + c3];
        g_XW[(nb + row) * C3 + c3] = a;
    }
}

// ---------------- kernel 6: GCN agg + bias + relu + pool + state reset -------
__global__ void k_gcn(const int* __restrict__ src, const float* __restrict__ gw,
                      const int* __restrict__ seg, const float* __restrict__ gcn_b,
                      float* __restrict__ out) {
    int gthr = blockIdx.x * blockDim.x + threadIdx.x;
    int t = gthr >> 5;
    int lane = threadIdx.x & 31;
    if (t >= N_NODES) return;
    if (lane == 0) g_deg[t] = 0;
    if (gthr < 65) g_chainflag[gthr] = 0;
    if (gthr == 65) g_done = 0;

    int rs = g_rowptr[t], re = g_rowptr[t + 1];
    float acc = gw[N_EDGES + t] * g_XW[t * C3 + lane];    // self loop
    int pos = rs;
    int eid = 0, s = 0;
    if (pos < re) { eid = g_csr[pos]; s = src[eid]; }
    while (pos < re) {
        float xv = g_XW[s * C3 + lane];
        float wv = gw[eid];
        int pos2 = pos + 1;
        int eid2 = 0, s2 = 0;
        if (pos2 < re) { eid2 = g_csr[pos2]; s2 = src[eid2]; }
        acc += wv * xv;
        pos = pos2; eid = eid2; s = s2;
    }
    float v = fmaxf(acc + gcn_b[lane], 0.f);
    atomicAdd(&out[seg[t] * C3 + lane], v);
}

// =============================================================================
extern "C" void kernel_launch(void* const* d_in, const int* in_sizes, int n_in,
                              void* d_out, int out_size) {
    const float* x       = (const float*)d_in[0];
    const float* e       = (const float*)d_in[1];
    const int*   src     = (const int*)d_in[2];
    const int*   tgt     = (const int*)d_in[3];
    const int*   seg     = (const int*)d_in[4];
    const float* gw      = (const float*)d_in[7];
    const float* e1_w0   = (const float*)d_in[8];
    const float* e1_b0   = (const float*)d_in[9];
    const float* e1_w1   = (const float*)d_in[10];
    const float* e1_b1   = (const float*)d_in[11];
    const float* e1_wk   = (const float*)d_in[12];
    const float* e1_bk   = (const float*)d_in[13];
    const float* e1_root = (const float*)d_in[14];
    const float* e1_bias = (const float*)d_in[15];
    const float* e2_w0   = (const float*)d_in[16];
    const float* e2_b0   = (const float*)d_in[17];
    const float* e2_w1   = (const float*)d_in[18];
    const float* e2_b1   = (const float*)d_in[19];
    const float* e2_wk   = (const float*)d_in[20];
    const float* e2_bk   = (const float*)d_in[21];
    const float* e2_root = (const float*)d_in[22];
    const float* e2_bias = (const float*)d_in[23];
    const float* gcn_W   = (const float*)d_in[24];
    const float* gcn_b   = (const float*)d_in[25];
    float* out = (float*)d_out;

    k_mlp<<<N_EDGES / 256, 256>>>(e, tgt, e1_w0, e1_b0, e1_w1, e1_b1,
                                  e2_w0, e2_b0, e2_w1, e2_b1,
                                  out, out_size,
                                  e1_wk, e1_bk, e1_root, e2_wk, e2_bk, e2_root);
    k_csr<<<64, 256>>>(tgt);
    k_ecc1<<<N_NODES / 8, 256>>>(x, src, e1_bias);
    k_p2<<<N_NODES / 8, 256>>>(src);
    k_gemm2<<<N_NODES / 128, 256>>>(e2_bias, gcn_W);
    k_gcn<<<(N_NODES * 32) / 256, 256>>>(src, gw, seg, gcn_b, out);
}

// round 12
// speedup vs baseline: 1.0553x; 1.0484x over previous
#include <cuda_runtime.h>

#define N_NODES 16384
#define N_EDGES 131072
#define F_IN 6
#define S_DIM 4
#define G_NUM 256
#define H_DIM 30
#define HSTR 32         /* padded h-row stride (128B-aligned rows) */
#define C1 32
#define C2 64
#define C3 32
#define K1 192          /* 30*6 wk1 + 6 bk1 + 6 root1 */
#define K2 1024         /* permuted: j*64+2*c1+par (h=2j+par) | 960+c1 bk | 992+c1 root */

// ---------------- scratch ----------------------------------------------------
__device__ float g_H1[N_EDGES * HSTR];
__device__ float g_H2[N_EDGES * HSTR];
__device__ float g_P2[N_NODES * K2];
__device__ float g_X1[N_NODES * C1];
__device__ float g_XW[N_NODES * C3];
__device__ float g_W1[K1 * C1];
__device__ float g_W2[K2 * C2];
__device__ int g_deg[N_NODES];          // left zero by k_gcn for the next call
__device__ int g_rowptr[N_NODES + 1];
__device__ int g_cursor[N_NODES];
__device__ int g_csr[N_EDGES];
__device__ int g_chainflag[65];         // prefix+1; 0 = not ready
__device__ int g_done;

// ---------------- packed f32x2 helpers ---------------------------------------
__device__ __forceinline__ unsigned long long pk2(float lo, float hi) {
    unsigned long long r;
    asm("mov.b64 %0, {%1, %2};" : "=l"(r) : "f"(lo), "f"(hi));
    return r;
}
__device__ __forceinline__ void upk2(unsigned long long v, float& lo, float& hi) {
    asm("mov.b64 {%0, %1}, %2;" : "=f"(lo), "=f"(hi) : "l"(v));
}
__device__ __forceinline__ unsigned long long fma2(unsigned long long a,
                                                   unsigned long long b,
                                                   unsigned long long c) {
    unsigned long long d;
    asm("fma.rn.f32x2 %0, %1, %2, %3;" : "=l"(d) : "l"(a), "l"(b), "l"(c));
    return d;
}

// ---------------- kernel 1: edge MLPs + tgt hist + prep (merged) -------------
__global__ void k_mlp(const float* __restrict__ e, const int* __restrict__ tgt,
                      const float* __restrict__ w0a, const float* __restrict__ b0a,
                      const float* __restrict__ w1a, const float* __restrict__ b1a,
                      const float* __restrict__ w0b, const float* __restrict__ b0b,
                      const float* __restrict__ w1b, const float* __restrict__ b1b,
                      float* __restrict__ out, int out_n,
                      const float* __restrict__ e1_wk, const float* __restrict__ e1_bk,
                      const float* __restrict__ e1_root,
                      const float* __restrict__ e2_wk, const float* __restrict__ e2_bk,
                      const float* __restrict__ e2_root) {
    __shared__ float sw0[2][S_DIM * H_DIM];
    __shared__ float sb0[2][H_DIM];
    __shared__ float sw1[2][H_DIM * H_DIM];
    __shared__ float sb1[2][H_DIM];
    for (int i = threadIdx.x; i < S_DIM * H_DIM; i += blockDim.x) {
        sw0[0][i] = w0a[i]; sw0[1][i] = w0b[i];
    }
    for (int i = threadIdx.x; i < H_DIM; i += blockDim.x) {
        sb0[0][i] = b0a[i]; sb0[1][i] = b0b[i];
        sb1[0][i] = b1a[i]; sb1[1][i] = b1b[i];
    }
    for (int i = threadIdx.x; i < H_DIM * H_DIM; i += blockDim.x) {
        sw1[0][i] = w1a[i]; sw1[1][i] = w1b[i];
    }
    __syncthreads();

    int eid = blockIdx.x * blockDim.x + threadIdx.x;
    if (eid >= N_EDGES) return;

    // ---- prep duties spread over the grid ----
    if (eid < out_n) out[eid] = 0.f;
    if (eid < K1 * C1) {
        int k = eid / C1, c = eid % C1;
        float v;
        if (k < 180)      { int h = k / 6, f = k % 6; v = e1_wk[h * (F_IN * C1) + f * C1 + c]; }
        else if (k < 186) { int f = k - 180;          v = e1_bk[f * C1 + c]; }
        else              { int f = k - 186;          v = e1_root[f * C1 + c]; }
        g_W1[eid] = v;
    }
    if (eid < K2 * C2) {
        int k = eid / C2, c = eid % C2;
        float v;
        if (k < 960) {      // permuted: k = j*64 + 2*c1 + par, h = 2j+par
            int j = k >> 6, r = k & 63, c1 = r >> 1, par = r & 1, h = 2 * j + par;
            v = e2_wk[h * (C1 * C2) + c1 * C2 + c];
        }
        else if (k < 992) { int c1 = k - 960; v = e2_bk[c1 * C2 + c]; }
        else              { int c1 = k - 992; v = e2_root[c1 * C2 + c]; }
        g_W2[eid] = v;
    }

    atomicAdd(&g_deg[tgt[eid]], 1);

    float4 ev4 = *reinterpret_cast<const float4*>(e + eid * 4);
    float ev[4] = {ev4.x, ev4.y, ev4.z, ev4.w};

    #pragma unroll
    for (int set = 0; set < 2; set++) {
        unsigned long long h0p[15];
        #pragma unroll
        for (int j = 0; j < 15; j++)
            h0p[j] = *reinterpret_cast<const unsigned long long*>(&sb0[set][2 * j]);
        #pragma unroll
        for (int s = 0; s < S_DIM; s++) {
            unsigned long long ep = pk2(ev[s], ev[s]);
            #pragma unroll
            for (int j = 0; j < 15; j++) {
                unsigned long long wp =
                    *reinterpret_cast<const unsigned long long*>(&sw0[set][s * H_DIM + 2 * j]);
                h0p[j] = fma2(wp, ep, h0p[j]);
            }
        }
        float h0[H_DIM];
        #pragma unroll
        for (int j = 0; j < 15; j++) {
            float a, b;
            upk2(h0p[j], a, b);
            h0[2 * j] = fmaxf(a, 0.f);
            h0[2 * j + 1] = fmaxf(b, 0.f);
        }
        unsigned long long h1p[15];
        #pragma unroll
        for (int j = 0; j < 15; j++)
            h1p[j] = *reinterpret_cast<const unsigned long long*>(&sb1[set][2 * j]);
        #pragma unroll 6
        for (int k = 0; k < H_DIM; k++) {
            unsigned long long hp = pk2(h0[k], h0[k]);
            #pragma unroll
            for (int j = 0; j < 15; j++) {
                unsigned long long wp =
                    *reinterpret_cast<const unsigned long long*>(&sw1[set][k * H_DIM + 2 * j]);
                h1p[j] = fma2(wp, hp, h1p[j]);
            }
        }
        float* dst = (set == 0 ? g_H1 : g_H2) + eid * HSTR;
        #pragma unroll
        for (int j = 0; j < 15; j++) {
            float a, b;
            upk2(h1p[j], a, b);
            *reinterpret_cast<unsigned long long*>(dst + 2 * j) = pk2(fmaxf(a, 0.f), fmaxf(b, 0.f));
        }
    }
}

// ---------------- kernel 2: full CSR build in ONE kernel ----------------------
__global__ void k_csr(const int* __restrict__ tgt) {
    __shared__ int sh[256];
    __shared__ int s_prefix;
    int tid = threadIdx.x, b = blockIdx.x;
    int i = b * 256 + tid;
    int v = g_deg[i];
    sh[tid] = v;
    __syncthreads();
    int sum = v;
    for (int d = 1; d < 256; d <<= 1) {
        int t = (tid >= d) ? sh[tid - d] : 0;
        __syncthreads();
        sum += t;
        sh[tid] = sum;
        __syncthreads();
    }
    if (tid == 0) {
        int p = 0;
        if (b > 0) {
            while ((p = atomicAdd(&g_chainflag[b], 0)) == 0) {}
            p -= 1;
        }
        s_prefix = p;
        atomicExch(&g_chainflag[b + 1], p + sh[255] + 1);
    }
    __syncthreads();
    int r = s_prefix + sum - v;
    g_rowptr[i] = r;
    g_cursor[i] = r;
    if (b == 63 && tid == 255) g_rowptr[N_NODES] = N_EDGES;
    __threadfence();
    __syncthreads();
    if (tid == 0) atomicAdd(&g_done, 1);
    if (tid == 0) { while (atomicAdd(&g_done, 0) < 64) {} }
    __syncthreads();
    for (int e = b * 2048 + tid; e < (b + 1) * 2048; e += 256) {
        int p = atomicAdd(&g_cursor[tgt[e]], 1);
        g_csr[p] = e;
    }
}

// ---------------- kernel 3: fused ECC1 (P1 rows in smem + mini-GEMM) ---------
// block = 256 threads = 8 warps = 8 targets; lane = K1-row (0..29 wk,30 bk,31 root)
__global__ void k_ecc1(const float* __restrict__ x, const int* __restrict__ src,
                       const float* __restrict__ bias1) {
    __shared__ float sW1[K1 * C1];      // 24 KB
    __shared__ float sP1[8][K1];        // 6 KB
    int tid = threadIdx.x;
    int w = tid >> 5, lane = tid & 31;
    int t = blockIdx.x * 8 + w;
    for (int i = tid; i < K1 * C1 / 4; i += 256)
        ((float4*)sW1)[i] = ((const float4*)g_W1)[i];

    int rs = g_rowptr[t], re = g_rowptr[t + 1];
    unsigned long long acc2[3] = {0ull, 0ull, 0ull};
    float hv_fix = (lane == 30) ? 1.f : 0.f;
    int pos = rs;
    int eid = 0, s = 0;
    if (pos < re) { eid = g_csr[pos]; s = src[eid]; }
    while (pos < re) {
        // warp-uniform x row (3 x LDG.64 broadcast)
        const unsigned long long* xp = reinterpret_cast<const unsigned long long*>(x + s * 6);
        unsigned long long x01 = xp[0], x23 = xp[1], x45 = xp[2];
        float hv = (lane < 30) ? g_H1[eid * HSTR + lane] : hv_fix;
        int pos2 = pos + 1;
        int eid2 = 0, s2 = 0;
        if (pos2 < re) { eid2 = g_csr[pos2]; s2 = src[eid2]; }
        unsigned long long hp = pk2(hv, hv);
        acc2[0] = fma2(x01, hp, acc2[0]);
        acc2[1] = fma2(x23, hp, acc2[1]);
        acc2[2] = fma2(x45, hp, acc2[2]);
        pos = pos2; eid = eid2; s = s2;
    }
    float acc[6];
    upk2(acc2[0], acc[0], acc[1]);
    upk2(acc2[1], acc[2], acc[3]);
    upk2(acc2[2], acc[4], acc[5]);
    if (lane == 31) {
        #pragma unroll
        for (int f = 0; f < 6; f++) acc[f] = x[t * 6 + f];
    }
    #pragma unroll
    for (int f = 0; f < 6; f++) sP1[w][lane * 6 + f] = acc[f];
    __syncthreads();

    float av = bias1[lane];
    const float* pr = sP1[w];
    #pragma unroll 8
    for (int k = 0; k < K1; k += 4) {
        float4 p = *reinterpret_cast<const float4*>(pr + k);
        av += p.x * sW1[(k + 0) * C1 + lane];
        av += p.y * sW1[(k + 1) * C1 + lane];
        av += p.z * sW1[(k + 2) * C1 + lane];
        av += p.w * sW1[(k + 3) * C1 + lane];
    }
    g_X1[t * C1 + lane] = fmaxf(av, 0.f);
}

// ---------------- kernel 4: P2, 2 warps per target ---------------------------
// lane = c1. Warp half 0: h-pairs j=0..7; half 1: j=8..14 + row30 + root row.
// Permuted store: k' = j*64 + 2*lane + par (h = 2j+par).
__global__ void k_p2(const int* __restrict__ src) {
    int tid = threadIdx.x;
    int w = tid >> 5, lane = tid & 31;
    int half = w & 1;
    int t = blockIdx.x * 4 + (w >> 1);
    int rs = g_rowptr[t], re = g_rowptr[t + 1];
    float* base = g_P2 + t * K2;

    if (half == 0) {
        unsigned long long acc2[8];
        #pragma unroll
        for (int j = 0; j < 8; j++) acc2[j] = 0ull;
        int pos = rs;
        int eid = 0, s = 0;
        if (pos < re) { eid = g_csr[pos]; s = src[eid]; }
        while (pos < re) {
            float x1v = g_X1[s * C1 + lane];
            const unsigned long long* hp =
                reinterpret_cast<const unsigned long long*>(g_H2 + eid * HSTR);
            int pos2 = pos + 1;
            int eid2 = 0, s2 = 0;
            if (pos2 < re) { eid2 = g_csr[pos2]; s2 = src[eid2]; }
            unsigned long long xp = pk2(x1v, x1v);
            #pragma unroll
            for (int j = 0; j < 8; j++)
                acc2[j] = fma2(hp[j], xp, acc2[j]);
            pos = pos2; eid = eid2; s = s2;
        }
        #pragma unroll
        for (int j = 0; j < 8; j++)
            *reinterpret_cast<unsigned long long*>(base + j * 64 + lane * 2) = acc2[j];
    } else {
        unsigned long long acc2[7];
        #pragma unroll
        for (int j = 0; j < 7; j++) acc2[j] = 0ull;
        float acc30 = 0.f;
        int pos = rs;
        int eid = 0, s = 0;
        if (pos < re) { eid = g_csr[pos]; s = src[eid]; }
        while (pos < re) {
            float x1v = g_X1[s * C1 + lane];
            const unsigned long long* hp =
                reinterpret_cast<const unsigned long long*>(g_H2 + eid * HSTR) + 8;
            int pos2 = pos + 1;
            int eid2 = 0, s2 = 0;
            if (pos2 < re) { eid2 = g_csr[pos2]; s2 = src[eid2]; }
            unsigned long long xp = pk2(x1v, x1v);
            #pragma unroll
            for (int j = 0; j < 7; j++)
                acc2[j] = fma2(hp[j], xp, acc2[j]);
            acc30 += x1v;
            pos = pos2; eid = eid2; s = s2;
        }
        #pragma unroll
        for (int j = 0; j < 7; j++)
            *reinterpret_cast<unsigned long long*>(base + (j + 8) * 64 + lane * 2) = acc2[j];
        base[960 + lane] = acc30;
        base[992 + lane] = g_X1[t * C1 + lane];
    }
}

// ---------------- kernel 5: GEMM2 + fused GCN-xw -----------------------------
__global__ void k_gemm2(const float* __restrict__ bias2, const float* __restrict__ gcnW) {
    __shared__ float smu[128 * 68];
    __shared__ float sW[C2 * C3];
    float* sA = smu;
    float* sB = smu + 4160;
    int tid = threadIdx.x;
    int nb = blockIdx.x * 128;
    for (int i = tid; i < C2 * C3; i += 256) sW[i] = gcnW[i];

    int tx = tid & 15;
    int ty = tid >> 4;
    unsigned long long acc2[4][4];
    #pragma unroll
    for (int p = 0; p < 4; p++)
        #pragma unroll
        for (int j = 0; j < 4; j++) acc2[p][j] = 0ull;

    for (int k0 = 0; k0 < K2; k0 += 32) {
        int lrow = tid >> 3, lk4 = (tid & 7) * 4;
        #pragma unroll
        for (int j = 0; j < 4; j++) {
            int row = lrow + 32 * j;
            float4 v = *reinterpret_cast<const float4*>(&g_P2[(nb + row) * K2 + k0 + lk4]);
            sA[(lk4 + 0) * 130 + row] = v.x;
            sA[(lk4 + 1) * 130 + row] = v.y;
            sA[(lk4 + 2) * 130 + row] = v.z;
            sA[(lk4 + 3) * 130 + row] = v.w;
        }
        {
            int kr = tid >> 3, c8 = (tid & 7) * 8;
            float4 v0 = *reinterpret_cast<const float4*>(&g_W2[(k0 + kr) * C2 + c8]);
            float4 v1 = *reinterpret_cast<const float4*>(&g_W2[(k0 + kr) * C2 + c8 + 4]);
            *reinterpret_cast<float4*>(&sB[kr * 64 + c8])     = v0;
            *reinterpret_cast<float4*>(&sB[kr * 64 + c8 + 4]) = v1;
        }
        __syncthreads();
        #pragma unroll 8
        for (int k = 0; k < 32; k++) {
            unsigned long long a[4];
            #pragma unroll
            for (int p = 0; p < 4; p++)
                a[p] = *reinterpret_cast<const unsigned long long*>(&sA[k * 130 + ty * 8 + p * 2]);
            float4 b = *reinterpret_cast<const float4*>(&sB[k * 64 + tx * 4]);
            float bb[4] = {b.x, b.y, b.z, b.w};
            #pragma unroll
            for (int j = 0; j < 4; j++) {
                unsigned long long bp = pk2(bb[j], bb[j]);
                #pragma unroll
                for (int p = 0; p < 4; p++) acc2[p][j] = fma2(a[p], bp, acc2[p][j]);
            }
        }
        __syncthreads();
    }
    float* sX2 = smu;
    #pragma unroll
    for (int p = 0; p < 4; p++)
        #pragma unroll
        for (int j = 0; j < 4; j++) {
            float v0, v1;
            upk2(acc2[p][j], v0, v1);
            int c = tx * 4 + j;
            float bs = bias2[c];
            int r0 = ty * 8 + p * 2;
            sX2[r0 * 68 + c]       = fmaxf(v0 + bs, 0.f);
            sX2[(r0 + 1) * 68 + c] = fmaxf(v1 + bs, 0.f);
        }
    __syncthreads();
    #pragma unroll
    for (int i = 0; i < 16; i++) {
        int o = tid + i * 256;
        int row = o >> 5, c3 = o & 31;
        float a = 0.f;
        #pragma unroll 8
        for (int c2 = 0; c2 < C2; c2++)
            a += sX2[row * 68 + c2] * sW[c2 * C3 + c3];
        g_XW[(nb + row) * C3 + c3] = a;
    }
}

// ---------------- kernel 6: GCN agg + bias + relu + pool + state reset -------
__global__ void k_gcn(const int* __restrict__ src, const float* __restrict__ gw,
                      const int* __restrict__ seg, const float* __restrict__ gcn_b,
                      float* __restrict__ out) {
    int gthr = blockIdx.x * blockDim.x + threadIdx.x;
    int t = gthr >> 5;
    int lane = threadIdx.x & 31;
    if (t >= N_NODES) return;
    if (lane == 0) g_deg[t] = 0;
    if (gthr < 65) g_chainflag[gthr] = 0;
    if (gthr == 65) g_done = 0;

    int rs = g_rowptr[t], re = g_rowptr[t + 1];
    float acc = gw[N_EDGES + t] * g_XW[t * C3 + lane];    // self loop
    int pos = rs;
    int eid = 0, s = 0;
    if (pos < re) { eid = g_csr[pos]; s = src[eid]; }
    while (pos < re) {
        float xv = g_XW[s * C3 + lane];
        float wv = gw[eid];
        int pos2 = pos + 1;
        int eid2 = 0, s2 = 0;
        if (pos2 < re) { eid2 = g_csr[pos2]; s2 = src[eid2]; }
        acc += wv * xv;
        pos = pos2; eid = eid2; s = s2;
    }
    float v = fmaxf(acc + gcn_b[lane], 0.f);
    atomicAdd(&out[seg[t] * C3 + lane], v);
}

// =============================================================================
extern "C" void kernel_launch(void* const* d_in, const int* in_sizes, int n_in,
                              void* d_out, int out_size) {
    const float* x       = (const float*)d_in[0];
    const float* e       = (const float*)d_in[1];
    const int*   src     = (const int*)d_in[2];
    const int*   tgt     = (const int*)d_in[3];
    const int*   seg     = (const int*)d_in[4];
    const float* gw      = (const float*)d_in[7];
    const float* e1_w0   = (const float*)d_in[8];
    const float* e1_b0   = (const float*)d_in[9];
    const float* e1_w1   = (const float*)d_in[10];
    const float* e1_b1   = (const float*)d_in[11];
    const float* e1_wk   = (const float*)d_in[12];
    const float* e1_bk   = (const float*)d_in[13];
    const float* e1_root = (const float*)d_in[14];
    const float* e1_bias = (const float*)d_in[15];
    const float* e2_w0   = (const float*)d_in[16];
    const float* e2_b0   = (const float*)d_in[17];
    const float* e2_w1   = (const float*)d_in[18];
    const float* e2_b1   = (const float*)d_in[19];
    const float* e2_wk   = (const float*)d_in[20];
    const float* e2_bk   = (const float*)d_in[21];
    const float* e2_root = (const float*)d_in[22];
    const float* e2_bias = (const float*)d_in[23];
    const float* gcn_W   = (const float*)d_in[24];
    const float* gcn_b   = (const float*)d_in[25];
    float* out = (float*)d_out;

    k_mlp<<<N_EDGES / 256, 256>>>(e, tgt, e1_w0, e1_b0, e1_w1, e1_b1,
                                  e2_w0, e2_b0, e2_w1, e2_b1,
                                  out, out_size,
                                  e1_wk, e1_bk, e1_root, e2_wk, e2_bk, e2_root);
    k_csr<<<64, 256>>>(tgt);
    k_ecc1<<<N_NODES / 8, 256>>>(x, src, e1_bias);
    k_p2<<<N_NODES / 4, 256>>>(src);
    k_gemm2<<<N_NODES / 128, 256>>>(e2_bias, gcn_W);
    k_gcn<<<(N_NODES * 32) / 256, 256>>>(src, gw, seg, gcn_b, out);
}